// round 1
// baseline (speedup 1.0000x reference)
#include <cuda_runtime.h>
#include <cuda_bf16.h>

#define NN 20000
#define NE 320000
#define F0 10
#define F1 256
#define F2 128

// ---------------- scratch (device globals; no allocation allowed) ----------
__device__ int   g_cnt[NN];
__device__ int   g_rowptr[NN + 1];
__device__ int   g_woff[NN];
__device__ int   g_csr[NE];          // src index per CSR slot (grouped by dst)
__device__ float g_dinv[NN];
__device__ float g_aggx[NN * F0];    // A_norm @ x
__device__ float g_h1[NN * F1];      // relu(aggx @ W1 + b1)
__device__ float g_t2[NN * F2];      // h1 @ W2
__device__ float g_h2[NN * F2];      // relu(A_norm @ t2 + b2)
__device__ float g_t3[NN];           // h2 @ W3

// ---------------- CSR build ------------------------------------------------
__global__ void k_zero_cnt() {
    int i = blockIdx.x * blockDim.x + threadIdx.x;
    if (i < NN) g_cnt[i] = 0;
}

__global__ void k_hist(const int* __restrict__ dst) {
    int e = blockIdx.x * blockDim.x + threadIdx.x;
    if (e < NE) atomicAdd(&g_cnt[dst[e]], 1);
}

__global__ void k_dinv() {
    int i = blockIdx.x * blockDim.x + threadIdx.x;
    if (i < NN) g_dinv[i] = rsqrtf((float)(g_cnt[i] + 1));  // +1 self loop
}

// single-block exclusive scan of g_cnt -> g_rowptr (and g_woff copy)
__global__ void k_scan() {
    __shared__ int warp_tot[32];
    __shared__ int block_tot;
    __shared__ int carry_s;
    int tid = threadIdx.x;
    if (tid == 0) carry_s = 0;
    __syncthreads();
    for (int base = 0; base < NN; base += 1024) {
        int i = base + tid;
        int v = (i < NN) ? g_cnt[i] : 0;
        int s = v;
        #pragma unroll
        for (int o = 1; o < 32; o <<= 1) {
            int t = __shfl_up_sync(0xffffffffu, s, o);
            if ((tid & 31) >= o) s += t;
        }
        if ((tid & 31) == 31) warp_tot[tid >> 5] = s;
        __syncthreads();
        if (tid < 32) {
            int t = warp_tot[tid];
            int ss = t;
            #pragma unroll
            for (int o = 1; o < 32; o <<= 1) {
                int u = __shfl_up_sync(0xffffffffu, ss, o);
                if (tid >= o) ss += u;
            }
            warp_tot[tid] = ss - t;          // exclusive warp offsets
            if (tid == 31) block_tot = ss;   // chunk total
        }
        __syncthreads();
        int excl = carry_s + warp_tot[tid >> 5] + s - v;
        if (i < NN) { g_rowptr[i] = excl; g_woff[i] = excl; }
        __syncthreads();
        if (tid == 0) carry_s += block_tot;
        __syncthreads();
    }
    if (tid == 0) g_rowptr[NN] = carry_s;
}

__global__ void k_scatter(const int* __restrict__ src, const int* __restrict__ dst) {
    int e = blockIdx.x * blockDim.x + threadIdx.x;
    if (e < NE) {
        int pos = atomicAdd(&g_woff[dst[e]], 1);
        g_csr[pos] = src[e];
    }
}

// ---------------- layer 1: aggregate x (F=10), then GEMM -------------------
__global__ void k_aggx(const float* __restrict__ x) {
    int w = (blockIdx.x * blockDim.x + threadIdx.x) >> 5;
    int lane = threadIdx.x & 31;
    if (w >= NN) return;
    float dn = g_dinv[w];
    float acc = 0.f;
    if (lane < F0) acc = dn * x[w * F0 + lane];
    int b = g_rowptr[w], e = g_rowptr[w + 1];
    for (int i = b; i < e; i++) {
        int s = g_csr[i];
        float c = g_dinv[s];
        if (lane < F0) acc += c * x[s * F0 + lane];
    }
    if (lane < F0) g_aggx[w * F0 + lane] = dn * acc;
}

// [NN,10] @ [10,256] + b1, relu.  20 rows per block, 256 threads = 1 col each.
__global__ void k_gemm1(const float* __restrict__ W1, const float* __restrict__ b1) {
    __shared__ float Ws[F0 * F1];   // 10 KB
    __shared__ float bs[F1];
    __shared__ float ax[20 * F0];
    int t = threadIdx.x;
    for (int i = t; i < F0 * F1; i += 256) Ws[i] = W1[i];
    bs[t] = b1[t];
    int r0 = blockIdx.x * 20;
    for (int i = t; i < 20 * F0; i += 256) ax[i] = g_aggx[r0 * F0 + i];
    __syncthreads();
    #pragma unroll 4
    for (int r = 0; r < 20; r++) {
        float acc = bs[t];
        #pragma unroll
        for (int k = 0; k < F0; k++) acc += ax[r * F0 + k] * Ws[k * F1 + t];
        g_h1[(r0 + r) * F1 + t] = fmaxf(acc, 0.f);
    }
}

// ---------------- layer 2 GEMM: [NN,256] @ [256,128] -> g_t2 ---------------
// Tile: 32 rows x 128 cols, k-tile 32, 256 threads, 4x4 register tile.
__global__ void k_gemm2(const float* __restrict__ W2) {
    __shared__ float hs[32][33];
    __shared__ float ws[32][128];
    int t  = threadIdx.x;
    int tx = t & 31;         // col group 0..31 (4 cols each)
    int ty = t >> 5;         // row group 0..7 (4 rows each)
    int r0 = blockIdx.x * 32;
    float acc[4][4];
    #pragma unroll
    for (int i = 0; i < 4; i++)
        #pragma unroll
        for (int j = 0; j < 4; j++) acc[i][j] = 0.f;

    int li = t >> 3;               // 0..31 row for hs load
    int lk = (t & 7) * 4;          // k offset for hs load
    for (int k0 = 0; k0 < F1; k0 += 32) {
        float4 hv = *(const float4*)&g_h1[(r0 + li) * F1 + k0 + lk];
        hs[li][lk + 0] = hv.x; hs[li][lk + 1] = hv.y;
        hs[li][lk + 2] = hv.z; hs[li][lk + 3] = hv.w;
        #pragma unroll
        for (int p = 0; p < 4; p++) {
            int kk = ty + p * 8;
            *(float4*)&ws[kk][tx * 4] = *(const float4*)&W2[(k0 + kk) * F2 + tx * 4];
        }
        __syncthreads();
        #pragma unroll
        for (int kk = 0; kk < 32; kk++) {
            float4 bv = *(const float4*)&ws[kk][tx * 4];
            float a0 = hs[ty * 4 + 0][kk];
            float a1 = hs[ty * 4 + 1][kk];
            float a2 = hs[ty * 4 + 2][kk];
            float a3 = hs[ty * 4 + 3][kk];
            acc[0][0] += a0 * bv.x; acc[0][1] += a0 * bv.y; acc[0][2] += a0 * bv.z; acc[0][3] += a0 * bv.w;
            acc[1][0] += a1 * bv.x; acc[1][1] += a1 * bv.y; acc[1][2] += a1 * bv.z; acc[1][3] += a1 * bv.w;
            acc[2][0] += a2 * bv.x; acc[2][1] += a2 * bv.y; acc[2][2] += a2 * bv.z; acc[2][3] += a2 * bv.w;
            acc[3][0] += a3 * bv.x; acc[3][1] += a3 * bv.y; acc[3][2] += a3 * bv.z; acc[3][3] += a3 * bv.w;
        }
        __syncthreads();
    }
    #pragma unroll
    for (int i = 0; i < 4; i++) {
        float4 o = make_float4(acc[i][0], acc[i][1], acc[i][2], acc[i][3]);
        *(float4*)&g_t2[(r0 + ty * 4 + i) * F2 + tx * 4] = o;
    }
}

// ---------------- layer 2 aggregation (F=128), bias+relu -------------------
__global__ void k_agg2(const float* __restrict__ b2) {
    int w = (blockIdx.x * blockDim.x + threadIdx.x) >> 5;
    int lane = threadIdx.x & 31;
    if (w >= NN) return;
    float dn = g_dinv[w];
    int c4 = lane * 4;
    float4 sv = *(const float4*)&g_t2[w * F2 + c4];
    float4 acc = make_float4(dn * sv.x, dn * sv.y, dn * sv.z, dn * sv.w);
    int b = g_rowptr[w], e = g_rowptr[w + 1];
    for (int i = b; i < e; i++) {
        int s = g_csr[i];
        float c = g_dinv[s];
        float4 v = *(const float4*)&g_t2[s * F2 + c4];
        acc.x += c * v.x; acc.y += c * v.y; acc.z += c * v.z; acc.w += c * v.w;
    }
    float4 bb = *(const float4*)&b2[c4];
    float4 r;
    r.x = fmaxf(dn * acc.x + bb.x, 0.f);
    r.y = fmaxf(dn * acc.y + bb.y, 0.f);
    r.z = fmaxf(dn * acc.z + bb.z, 0.f);
    r.w = fmaxf(dn * acc.w + bb.w, 0.f);
    *(float4*)&g_h2[w * F2 + c4] = r;
}

// ---------------- layer 3 GEMV + aggregation -------------------------------
__global__ void k_dot3(const float* __restrict__ W3) {
    int w = (blockIdx.x * blockDim.x + threadIdx.x) >> 5;
    int lane = threadIdx.x & 31;
    if (w >= NN) return;
    float4 h = *(const float4*)&g_h2[w * F2 + lane * 4];
    float4 v = *(const float4*)&W3[lane * 4];
    float s = h.x * v.x + h.y * v.y + h.z * v.z + h.w * v.w;
    #pragma unroll
    for (int o = 16; o > 0; o >>= 1) s += __shfl_down_sync(0xffffffffu, s, o);
    if (lane == 0) g_t3[w] = s;
}

__global__ void k_agg3(const float* __restrict__ b3, float* __restrict__ out) {
    int n = blockIdx.x * blockDim.x + threadIdx.x;
    if (n >= NN) return;
    float dn = g_dinv[n];
    float acc = dn * g_t3[n];
    int b = g_rowptr[n], e = g_rowptr[n + 1];
    for (int i = b; i < e; i++) {
        int s = g_csr[i];
        acc += g_dinv[s] * g_t3[s];
    }
    out[n] = dn * acc + b3[0];
}

// ---------------- launch ----------------------------------------------------
extern "C" void kernel_launch(void* const* d_in, const int* in_sizes, int n_in,
                              void* d_out, int out_size) {
    const float* x   = (const float*)d_in[0];
    const int*   ei  = (const int*)d_in[1];
    const float* W1  = (const float*)d_in[2];
    const float* b1  = (const float*)d_in[3];
    const float* W2  = (const float*)d_in[4];
    const float* b2  = (const float*)d_in[5];
    const float* W3  = (const float*)d_in[6];
    const float* b3  = (const float*)d_in[7];
    float* out = (float*)d_out;
    const int* src = ei;
    const int* dst = ei + NE;

    k_zero_cnt<<<(NN + 255) / 256, 256>>>();
    k_hist<<<(NE + 255) / 256, 256>>>(dst);
    k_dinv<<<(NN + 255) / 256, 256>>>();
    k_scan<<<1, 1024>>>();
    k_scatter<<<(NE + 255) / 256, 256>>>(src, dst);

    k_aggx<<<(NN * 32 + 255) / 256, 256>>>(x);
    k_gemm1<<<NN / 20, 256>>>(W1, b1);
    k_gemm2<<<NN / 32, 256>>>(W2);
    k_agg2<<<(NN * 32 + 255) / 256, 256>>>(b2);
    k_dot3<<<(NN * 32 + 255) / 256, 256>>>(W3);
    k_agg3<<<(NN + 255) / 256, 256>>>(b3, out);
}